// round 9
// baseline (speedup 1.0000x reference)
#include <cuda_runtime.h>
#include <cuda_bf16.h>
#include <cstdint>

// Problem constants
#define B_  4
#define S_  128
#define D_  4096
#define H_  32
#define KV_ 8
#define HD_ 128
#define M_  (B_ * S_)          // 512 rows

// ---------------------------------------------------------------------------
// Scratch (device globals — no allocations allowed)
// ---------------------------------------------------------------------------
__device__ float g_q[M_ * H_ * HD_];    // 512 x 4096
__device__ float g_k[M_ * KV_ * HD_];   // 512 x 1024
__device__ float g_v[M_ * KV_ * HD_];   // 512 x 1024
__device__ float g_att[M_ * H_ * HD_];  // 512 x 4096

// bf16 split buffers
__device__ __nv_bfloat16 g_xh[M_ * D_],  g_xl[M_ * D_];        // x split
__device__ __nv_bfloat16 g_ah[M_ * D_],  g_al[M_ * D_];        // att split
__device__ __nv_bfloat16 g_wqh[D_ * D_], g_wql[D_ * D_];       // wq^T split  [N=4096][K=4096]
__device__ __nv_bfloat16 g_wkh[KV_ * HD_ * D_], g_wkl[KV_ * HD_ * D_];   // wk^T [1024][4096]
__device__ __nv_bfloat16 g_wvh[KV_ * HD_ * D_], g_wvl[KV_ * HD_ * D_];   // wv^T [1024][4096]
__device__ __nv_bfloat16 g_woh[D_ * D_], g_wol[D_ * D_];       // wo^T [4096][4096]

// ---------------------------------------------------------------------------
// Elementwise split: fp32 -> (hi, lo) bf16, hi = rn(x), lo = rn(x - hi)
// ---------------------------------------------------------------------------
__global__ void split_rows(const float* __restrict__ X,
                           __nv_bfloat16* __restrict__ Hh,
                           __nv_bfloat16* __restrict__ Ll, int n)
{
    int i = (blockIdx.x * blockDim.x + threadIdx.x) * 2;
    if (i >= n) return;
    float2 v = *(const float2*)(X + i);
    __nv_bfloat16 h0 = __float2bfloat16(v.x);
    __nv_bfloat16 h1 = __float2bfloat16(v.y);
    __nv_bfloat16 l0 = __float2bfloat16(v.x - __bfloat162float(h0));
    __nv_bfloat16 l1 = __float2bfloat16(v.y - __bfloat162float(h1));
    *(__nv_bfloat162*)(Hh + i) = __nv_bfloat162(h0, h1);
    *(__nv_bfloat162*)(Ll + i) = __nv_bfloat162(l0, l1);
}

// ---------------------------------------------------------------------------
// Transpose + split: W[K,N] fp32 -> Th[N,K], Tl[N,K] bf16.  32x32 smem tiles.
// ---------------------------------------------------------------------------
__global__ __launch_bounds__(256) void split_transpose(
    const float* __restrict__ W,
    __nv_bfloat16* __restrict__ Th, __nv_bfloat16* __restrict__ Tl,
    int K, int N)
{
    __shared__ float t[32][33];
    const int n0 = blockIdx.x * 32, k0 = blockIdx.y * 32;
    const int tx = threadIdx.x, ty = threadIdx.y;   // 32 x 8
#pragma unroll
    for (int r = 0; r < 32; r += 8)
        t[ty + r][tx] = W[(size_t)(k0 + ty + r) * N + n0 + tx];
    __syncthreads();
#pragma unroll
    for (int r = 0; r < 32; r += 8) {
        float v = t[tx][ty + r];
        __nv_bfloat16 h = __float2bfloat16(v);
        __nv_bfloat16 l = __float2bfloat16(v - __bfloat162float(h));
        size_t o = (size_t)(n0 + ty + r) * K + k0 + tx;
        Th[o] = h;
        Tl[o] = l;
    }
}

// ---------------------------------------------------------------------------
// Tensor-core GEMM with 2-term bf16 split:
//   C[M,N] = A[M,K] @ B^T[N,K] + bias[N]   (A, B given as hi/lo bf16 pairs)
// CTA tile 128x128, K-step 32, 8 warps (warp tile 64x32), cp.async dbl-buffer.
// ---------------------------------------------------------------------------
#define PADK 40                      // smem row stride (bf16 elems), 80B
#define GTILE (128 * PADK)           // one tile's elements
#define GSMEM (2 * 4 * GTILE * 2)    // bytes: 2 bufs x 4 tiles x bf16

__device__ __forceinline__ void cpa16(__nv_bfloat16* s, const __nv_bfloat16* g)
{
    uint32_t sa = (uint32_t)__cvta_generic_to_shared(s);
    asm volatile("cp.async.cg.shared.global [%0], [%1], 16;" :: "r"(sa), "l"(g));
}
__device__ __forceinline__ void cp_commit() { asm volatile("cp.async.commit_group;"); }
template <int N> __device__ __forceinline__ void cp_wait()
{
    asm volatile("cp.async.wait_group %0;" :: "n"(N));
}
__device__ __forceinline__ void mma16816(float* c, const uint32_t* a, const uint32_t* b)
{
    asm volatile(
        "mma.sync.aligned.m16n8k16.row.col.f32.bf16.bf16.f32 "
        "{%0,%1,%2,%3}, {%4,%5,%6,%7}, {%8,%9}, {%0,%1,%2,%3};"
        : "+f"(c[0]), "+f"(c[1]), "+f"(c[2]), "+f"(c[3])
        : "r"(a[0]), "r"(a[1]), "r"(a[2]), "r"(a[3]), "r"(b[0]), "r"(b[1]));
}

__global__ __launch_bounds__(256) void gemm_mma_split(
    const __nv_bfloat16* __restrict__ Ahi, const __nv_bfloat16* __restrict__ Alo,  // [M,K]
    const __nv_bfloat16* __restrict__ Bhi, const __nv_bfloat16* __restrict__ Blo,  // [N,K]
    const float* __restrict__ bias, float* __restrict__ C,
    int M, int N, int K)
{
    extern __shared__ __nv_bfloat16 smem[];

    const int tid  = threadIdx.x;
    const int lane = tid & 31;
    const int wid  = tid >> 5;
    const int grp  = lane >> 2;      // 0..7
    const int qid  = lane & 3;       // 0..3
    const int wm   = (wid & 1) * 64; // warp M offset
    const int wn   = (wid >> 1) * 32;// warp N offset
    const int rowA = blockIdx.y * 128;
    const int colB = blockIdx.x * 128;

    float acc[4][4][4];
#pragma unroll
    for (int i = 0; i < 4; i++)
#pragma unroll
        for (int j = 0; j < 4; j++)
#pragma unroll
            for (int q = 0; q < 4; q++) acc[i][j][q] = 0.0f;

    // tile loader: 4 tiles (Ahi, Alo, Bhi, Blo), each 128 rows x 32 bf16
    auto load_tiles = [&](int buf, int k0) {
        __nv_bfloat16* base = smem + buf * 4 * GTILE;
#pragma unroll
        for (int c = tid; c < 512; c += 256) {
            int row = c >> 2, off = (c & 3) * 8;
            size_t ga = (size_t)(rowA + row) * K + k0 + off;
            size_t gb = (size_t)(colB + row) * K + k0 + off;
            int so = row * PADK + off;
            cpa16(base + 0 * GTILE + so, Ahi + ga);
            cpa16(base + 1 * GTILE + so, Alo + ga);
            cpa16(base + 2 * GTILE + so, Bhi + gb);
            cpa16(base + 3 * GTILE + so, Blo + gb);
        }
    };

    const int NT = K / 32;
    load_tiles(0, 0);
    cp_commit();

    for (int kt = 0; kt < NT; kt++) {
        if (kt + 1 < NT) {
            load_tiles((kt + 1) & 1, (kt + 1) * 32);
            cp_commit();
            cp_wait<1>();
        } else {
            cp_wait<0>();
        }
        __syncthreads();

        const __nv_bfloat16* base = smem + (kt & 1) * 4 * GTILE;
        const __nv_bfloat16* sAh = base + 0 * GTILE;
        const __nv_bfloat16* sAl = base + 1 * GTILE;
        const __nv_bfloat16* sBh = base + 2 * GTILE;
        const __nv_bfloat16* sBl = base + 3 * GTILE;

#pragma unroll
        for (int kh = 0; kh < 2; kh++) {
            const int kb = (kh * 16 + qid * 2) >> 1;   // b32 index within row
            uint32_t ah[4][4], al[4][4], bh[4][2], bl[4][2];
#pragma unroll
            for (int mt = 0; mt < 4; mt++) {
                int r0 = wm + mt * 16 + grp;
                const uint32_t* p0h = (const uint32_t*)(sAh + r0 * PADK);
                const uint32_t* p1h = (const uint32_t*)(sAh + (r0 + 8) * PADK);
                const uint32_t* p0l = (const uint32_t*)(sAl + r0 * PADK);
                const uint32_t* p1l = (const uint32_t*)(sAl + (r0 + 8) * PADK);
                ah[mt][0] = p0h[kb];     ah[mt][1] = p1h[kb];
                ah[mt][2] = p0h[kb + 4]; ah[mt][3] = p1h[kb + 4];
                al[mt][0] = p0l[kb];     al[mt][1] = p1l[kb];
                al[mt][2] = p0l[kb + 4]; al[mt][3] = p1l[kb + 4];
            }
#pragma unroll
            for (int nt = 0; nt < 4; nt++) {
                int c0 = wn + nt * 8 + grp;
                const uint32_t* pbh = (const uint32_t*)(sBh + c0 * PADK);
                const uint32_t* pbl = (const uint32_t*)(sBl + c0 * PADK);
                bh[nt][0] = pbh[kb]; bh[nt][1] = pbh[kb + 4];
                bl[nt][0] = pbl[kb]; bl[nt][1] = pbl[kb + 4];
            }
#pragma unroll
            for (int mt = 0; mt < 4; mt++)
#pragma unroll
                for (int nt = 0; nt < 4; nt++) {
                    mma16816(acc[mt][nt], ah[mt], bh[nt]);
                    mma16816(acc[mt][nt], ah[mt], bl[nt]);
                    mma16816(acc[mt][nt], al[mt], bh[nt]);
                }
        }
        __syncthreads();
    }

    // epilogue: + bias, fp32 store
#pragma unroll
    for (int mt = 0; mt < 4; mt++) {
        int r = rowA + wm + mt * 16 + grp;
#pragma unroll
        for (int nt = 0; nt < 4; nt++) {
            int cc = colB + wn + nt * 8 + qid * 2;
            float b0 = bias[cc], b1 = bias[cc + 1];
            float2 v0 = make_float2(acc[mt][nt][0] + b0, acc[mt][nt][1] + b1);
            float2 v1 = make_float2(acc[mt][nt][2] + b0, acc[mt][nt][3] + b1);
            *(float2*)(C + (size_t)r * N + cc)       = v0;
            *(float2*)(C + (size_t)(r + 8) * N + cc) = v1;
        }
    }
}

// ---------------------------------------------------------------------------
// RoPE (unchanged)
// ---------------------------------------------------------------------------
__global__ void rope_kernel(float* __restrict__ t,
                            const float* __restrict__ fc,
                            const float* __restrict__ fs,
                            int nheads)
{
    int idx = blockIdx.x * blockDim.x + threadIdx.x;
    int total = B_ * S_ * nheads * (HD_ / 2);
    if (idx >= total) return;
    int p = idx & 63;
    int h = (idx >> 6) % nheads;
    int s = (idx / (64 * nheads)) % S_;
    int b = idx / (64 * nheads * S_);
    float c  = fc[s * 64 + p];
    float sn = fs[s * 64 + p];
    float* base = t + ((size_t)(b * S_ + s) * nheads + h) * HD_ + 2 * p;
    float re = base[0], im = base[1];
    base[0] = re * c - im * sn;
    base[1] = re * sn + im * c;
}

// ---------------------------------------------------------------------------
// Attention (unchanged from R1): one CTA per (b,h), fp32 SIMT
// ---------------------------------------------------------------------------
#define PAD 132
#define ATT_SMEM (3 * 128 * PAD * (int)sizeof(float))

__global__ __launch_bounds__(256) void attn_kernel(
    const float* __restrict__ q, const float* __restrict__ k,
    const float* __restrict__ v, float* __restrict__ o)
{
    extern __shared__ __align__(16) float sm[];
    float (*sQ)[PAD]  = (float(*)[PAD])sm;
    float (*sKt)[PAD] = (float(*)[PAD])(sm + 128 * PAD);
    float (*sS)[PAD]  = (float(*)[PAD])(sm + 2 * 128 * PAD);

    const int h = blockIdx.x;
    const int b = blockIdx.y;
    const int kvh = h >> 2;
    const int tx = threadIdx.x, ty = threadIdx.y;
    const int tid = ty * 16 + tx;

    for (int idx = tid; idx < 128 * 128; idx += 256) {
        int r = idx >> 7, c = idx & 127;
        sQ[r][c]  = q[((size_t)(b * S_ + r) * H_  + h)   * HD_ + c];
        sKt[c][r] = k[((size_t)(b * S_ + r) * KV_ + kvh) * HD_ + c];
    }
    __syncthreads();

    float acc[8][8];
#pragma unroll
    for (int i = 0; i < 8; i++)
#pragma unroll
        for (int j = 0; j < 8; j++) acc[i][j] = 0.0f;

#pragma unroll 4
    for (int d = 0; d < 128; d++) {
        float rA[8], rB[8];
#pragma unroll
        for (int i = 0; i < 8; i++) rA[i] = sQ[ty * 8 + i][d];
        float4 b0 = *(const float4*)&sKt[d][tx * 8];
        float4 b1 = *(const float4*)&sKt[d][tx * 8 + 4];
        rB[0] = b0.x; rB[1] = b0.y; rB[2] = b0.z; rB[3] = b0.w;
        rB[4] = b1.x; rB[5] = b1.y; rB[6] = b1.z; rB[7] = b1.w;
#pragma unroll
        for (int i = 0; i < 8; i++)
#pragma unroll
            for (int j = 0; j < 8; j++)
                acc[i][j] = fmaf(rA[i], rB[j], acc[i][j]);
    }

    const float scale = 0.08838834764831845f;
#pragma unroll
    for (int i = 0; i < 8; i++) {
        int r = ty * 8 + i;
#pragma unroll
        for (int j = 0; j < 8; j++) {
            int c = tx * 8 + j;
            sS[r][c] = (c <= r) ? acc[i][j] * scale : -1e30f;
        }
    }
    __syncthreads();

    {
        int wid = tid >> 5, lane = tid & 31;
        for (int r = wid; r < 128; r += 8) {
            float v0 = sS[r][lane],      v1 = sS[r][lane + 32];
            float v2 = sS[r][lane + 64], v3 = sS[r][lane + 96];
            float m = fmaxf(fmaxf(v0, v1), fmaxf(v2, v3));
#pragma unroll
            for (int o2 = 16; o2; o2 >>= 1) m = fmaxf(m, __shfl_xor_sync(0xffffffffu, m, o2));
            v0 = __expf(v0 - m); v1 = __expf(v1 - m);
            v2 = __expf(v2 - m); v3 = __expf(v3 - m);
            float s = v0 + v1 + v2 + v3;
#pragma unroll
            for (int o2 = 16; o2; o2 >>= 1) s += __shfl_xor_sync(0xffffffffu, s, o2);
            float inv = 1.0f / s;
            sS[r][lane]      = v0 * inv; sS[r][lane + 32] = v1 * inv;
            sS[r][lane + 64] = v2 * inv; sS[r][lane + 96] = v3 * inv;
        }
        float (*sV)[PAD] = sKt;
        for (int idx = tid; idx < 128 * 128; idx += 256) {
            int r = idx >> 7, c = idx & 127;
            sV[r][c] = v[((size_t)(b * S_ + r) * KV_ + kvh) * HD_ + c];
        }
    }
    __syncthreads();

    float (*sV)[PAD] = sKt;
#pragma unroll
    for (int i = 0; i < 8; i++)
#pragma unroll
        for (int j = 0; j < 8; j++) acc[i][j] = 0.0f;

#pragma unroll 4
    for (int j = 0; j < 128; j++) {
        float rA[8], rB[8];
#pragma unroll
        for (int i = 0; i < 8; i++) rA[i] = sS[ty * 8 + i][j];
        float4 b0 = *(const float4*)&sV[j][tx * 8];
        float4 b1 = *(const float4*)&sV[j][tx * 8 + 4];
        rB[0] = b0.x; rB[1] = b0.y; rB[2] = b0.z; rB[3] = b0.w;
        rB[4] = b1.x; rB[5] = b1.y; rB[6] = b1.z; rB[7] = b1.w;
#pragma unroll
        for (int i = 0; i < 8; i++)
#pragma unroll
            for (int jj = 0; jj < 8; jj++)
                acc[i][jj] = fmaf(rA[i], rB[jj], acc[i][jj]);
    }

#pragma unroll
    for (int i = 0; i < 8; i++) {
        int r = ty * 8 + i;
        float* dst = o + ((size_t)(b * S_ + r) * H_ + h) * HD_ + tx * 8;
        *(float4*)(dst)     = make_float4(acc[i][0], acc[i][1], acc[i][2], acc[i][3]);
        *(float4*)(dst + 4) = make_float4(acc[i][4], acc[i][5], acc[i][6], acc[i][7]);
    }
}

// ---------------------------------------------------------------------------
// Launch
// Inputs: 0:x 1:start_pos 2:freqs_cos 3:freqs_sin 4:mask 5:cache_k 6:cache_v
//         7:wq 8:bq 9:wk 10:bk 11:wv 12:bv 13:wo 14:bo
// ---------------------------------------------------------------------------
extern "C" void kernel_launch(void* const* d_in, const int* in_sizes, int n_in,
                              void* d_out, int out_size)
{
    const float* x    = (const float*)d_in[0];
    const float* fcos = (const float*)d_in[2];
    const float* fsin = (const float*)d_in[3];
    const float* wq   = (const float*)d_in[7];
    const float* bq   = (const float*)d_in[8];
    const float* wk   = (const float*)d_in[9];
    const float* bk   = (const float*)d_in[10];
    const float* wv   = (const float*)d_in[11];
    const float* bv   = (const float*)d_in[12];
    const float* wo   = (const float*)d_in[13];
    const float* bo   = (const float*)d_in[14];
    float* out = (float*)d_out;

    float *pq, *pk, *pv, *patt;
    __nv_bfloat16 *xh, *xl, *ah, *al;
    __nv_bfloat16 *wqh, *wql, *wkh, *wkl, *wvh, *wvl, *woh, *wol;
    cudaGetSymbolAddress((void**)&pq,   g_q);
    cudaGetSymbolAddress((void**)&pk,   g_k);
    cudaGetSymbolAddress((void**)&pv,   g_v);
    cudaGetSymbolAddress((void**)&patt, g_att);
    cudaGetSymbolAddress((void**)&xh,  g_xh);  cudaGetSymbolAddress((void**)&xl,  g_xl);
    cudaGetSymbolAddress((void**)&ah,  g_ah);  cudaGetSymbolAddress((void**)&al,  g_al);
    cudaGetSymbolAddress((void**)&wqh, g_wqh); cudaGetSymbolAddress((void**)&wql, g_wql);
    cudaGetSymbolAddress((void**)&wkh, g_wkh); cudaGetSymbolAddress((void**)&wkl, g_wkl);
    cudaGetSymbolAddress((void**)&wvh, g_wvh); cudaGetSymbolAddress((void**)&wvl, g_wvl);
    cudaGetSymbolAddress((void**)&woh, g_woh); cudaGetSymbolAddress((void**)&wol, g_wol);

    cudaFuncSetAttribute(attn_kernel, cudaFuncAttributeMaxDynamicSharedMemorySize, ATT_SMEM);
    cudaFuncSetAttribute(gemm_mma_split, cudaFuncAttributeMaxDynamicSharedMemorySize, GSMEM);

    // --- split activations + weights ---
    split_rows<<<(M_ * D_ / 2 + 255) / 256, 256>>>(x, xh, xl, M_ * D_);
    split_transpose<<<dim3(D_ / 32, D_ / 32), dim3(32, 8)>>>(wq, wqh, wql, D_, D_);
    split_transpose<<<dim3((KV_ * HD_) / 32, D_ / 32), dim3(32, 8)>>>(wk, wkh, wkl, D_, KV_ * HD_);
    split_transpose<<<dim3((KV_ * HD_) / 32, D_ / 32), dim3(32, 8)>>>(wv, wvh, wvl, D_, KV_ * HD_);
    split_transpose<<<dim3(D_ / 32, D_ / 32), dim3(32, 8)>>>(wo, woh, wol, D_, D_);

    // --- QKV projections (tensor core) ---
    gemm_mma_split<<<dim3((H_ * HD_) / 128, M_ / 128), 256, GSMEM>>>(
        xh, xl, wqh, wql, bq, pq, M_, H_ * HD_, D_);
    gemm_mma_split<<<dim3((KV_ * HD_) / 128, M_ / 128), 256, GSMEM>>>(
        xh, xl, wkh, wkl, bk, pk, M_, KV_ * HD_, D_);
    gemm_mma_split<<<dim3((KV_ * HD_) / 128, M_ / 128), 256, GSMEM>>>(
        xh, xl, wvh, wvl, bv, pv, M_, KV_ * HD_, D_);

    // --- RoPE ---
    {
        int tq = B_ * S_ * H_ * (HD_ / 2);
        int tk = B_ * S_ * KV_ * (HD_ / 2);
        rope_kernel<<<(tq + 255) / 256, 256>>>(pq, fcos, fsin, H_);
        rope_kernel<<<(tk + 255) / 256, 256>>>(pk, fcos, fsin, KV_);
    }

    // --- attention ---
    attn_kernel<<<dim3(H_, B_), dim3(16, 16), ATT_SMEM>>>(pq, pk, pv, patt);

    // --- output projection ---
    split_rows<<<(M_ * D_ / 2 + 255) / 256, 256>>>(patt, ah, al, M_ * D_);
    gemm_mma_split<<<dim3(D_ / 128, M_ / 128), 256, GSMEM>>>(
        ah, al, woh, wol, bo, out, M_, D_, D_);
}

// round 10
// speedup vs baseline: 1.0045x; 1.0045x over previous
#include <cuda_runtime.h>
#include <cuda_bf16.h>
#include <cstdint>

// Problem constants
#define B_  4
#define S_  128
#define D_  4096
#define H_  32
#define KV_ 8
#define HD_ 128
#define M_  (B_ * S_)          // 512 rows

// ---------------------------------------------------------------------------
// Scratch (device globals — no allocations allowed)
// ---------------------------------------------------------------------------
__device__ float g_q[M_ * H_ * HD_];    // 512 x 4096
__device__ float g_k[M_ * KV_ * HD_];   // 512 x 1024
__device__ float g_v[M_ * KV_ * HD_];   // 512 x 1024
__device__ float g_att[M_ * H_ * HD_];  // 512 x 4096

// bf16 split buffers
__device__ __nv_bfloat16 g_xh[M_ * D_],  g_xl[M_ * D_];        // x split
__device__ __nv_bfloat16 g_ah[M_ * D_],  g_al[M_ * D_];        // att split
__device__ __nv_bfloat16 g_wqh[D_ * D_], g_wql[D_ * D_];       // wq^T split  [N=4096][K=4096]
__device__ __nv_bfloat16 g_wkh[KV_ * HD_ * D_], g_wkl[KV_ * HD_ * D_];   // wk^T [1024][4096]
__device__ __nv_bfloat16 g_wvh[KV_ * HD_ * D_], g_wvl[KV_ * HD_ * D_];   // wv^T [1024][4096]
__device__ __nv_bfloat16 g_woh[D_ * D_], g_wol[D_ * D_];       // wo^T [4096][4096]

// ---------------------------------------------------------------------------
// Elementwise split: fp32 -> (hi, lo) bf16, hi = rn(x), lo = rn(x - hi)
// ---------------------------------------------------------------------------
__global__ void split_rows(const float* __restrict__ X,
                           __nv_bfloat16* __restrict__ Hh,
                           __nv_bfloat16* __restrict__ Ll, int n)
{
    int i = (blockIdx.x * blockDim.x + threadIdx.x) * 2;
    if (i >= n) return;
    float2 v = *(const float2*)(X + i);
    __nv_bfloat16 h0 = __float2bfloat16(v.x);
    __nv_bfloat16 h1 = __float2bfloat16(v.y);
    __nv_bfloat16 l0 = __float2bfloat16(v.x - __bfloat162float(h0));
    __nv_bfloat16 l1 = __float2bfloat16(v.y - __bfloat162float(h1));
    *(__nv_bfloat162*)(Hh + i) = __nv_bfloat162(h0, h1);
    *(__nv_bfloat162*)(Ll + i) = __nv_bfloat162(l0, l1);
}

// ---------------------------------------------------------------------------
// Transpose + split: W[K,N] fp32 -> Th[N,K], Tl[N,K] bf16.  32x32 smem tiles.
// ---------------------------------------------------------------------------
__global__ __launch_bounds__(256) void split_transpose(
    const float* __restrict__ W,
    __nv_bfloat16* __restrict__ Th, __nv_bfloat16* __restrict__ Tl,
    int K, int N)
{
    __shared__ float t[32][33];
    const int n0 = blockIdx.x * 32, k0 = blockIdx.y * 32;
    const int tx = threadIdx.x, ty = threadIdx.y;   // 32 x 8
#pragma unroll
    for (int r = 0; r < 32; r += 8)
        t[ty + r][tx] = W[(size_t)(k0 + ty + r) * N + n0 + tx];
    __syncthreads();
#pragma unroll
    for (int r = 0; r < 32; r += 8) {
        float v = t[tx][ty + r];
        __nv_bfloat16 h = __float2bfloat16(v);
        __nv_bfloat16 l = __float2bfloat16(v - __bfloat162float(h));
        size_t o = (size_t)(n0 + ty + r) * K + k0 + tx;
        Th[o] = h;
        Tl[o] = l;
    }
}

// ---------------------------------------------------------------------------
// Tensor-core GEMM with 2-term bf16 split:
//   C[M,N] = A[M,K] @ B^T[N,K] + bias[N]   (A, B given as hi/lo bf16 pairs)
// CTA tile 128x128, K-step 32, 8 warps (warp tile 64x32), cp.async dbl-buffer.
// ---------------------------------------------------------------------------
#define PADK 40                      // smem row stride (bf16 elems), 80B
#define GTILE (128 * PADK)           // one tile's elements
#define GSMEM (2 * 4 * GTILE * 2)    // bytes: 2 bufs x 4 tiles x bf16

__device__ __forceinline__ void cpa16(__nv_bfloat16* s, const __nv_bfloat16* g)
{
    uint32_t sa = (uint32_t)__cvta_generic_to_shared(s);
    asm volatile("cp.async.cg.shared.global [%0], [%1], 16;" :: "r"(sa), "l"(g));
}
__device__ __forceinline__ void cp_commit() { asm volatile("cp.async.commit_group;"); }
template <int N> __device__ __forceinline__ void cp_wait()
{
    asm volatile("cp.async.wait_group %0;" :: "n"(N));
}
__device__ __forceinline__ void mma16816(float* c, const uint32_t* a, const uint32_t* b)
{
    asm volatile(
        "mma.sync.aligned.m16n8k16.row.col.f32.bf16.bf16.f32 "
        "{%0,%1,%2,%3}, {%4,%5,%6,%7}, {%8,%9}, {%0,%1,%2,%3};"
        : "+f"(c[0]), "+f"(c[1]), "+f"(c[2]), "+f"(c[3])
        : "r"(a[0]), "r"(a[1]), "r"(a[2]), "r"(a[3]), "r"(b[0]), "r"(b[1]));
}

__global__ __launch_bounds__(256) void gemm_mma_split(
    const __nv_bfloat16* __restrict__ Ahi, const __nv_bfloat16* __restrict__ Alo,  // [M,K]
    const __nv_bfloat16* __restrict__ Bhi, const __nv_bfloat16* __restrict__ Blo,  // [N,K]
    const float* __restrict__ bias, float* __restrict__ C,
    int M, int N, int K)
{
    extern __shared__ __nv_bfloat16 smem[];

    const int tid  = threadIdx.x;
    const int lane = tid & 31;
    const int wid  = tid >> 5;
    const int grp  = lane >> 2;      // 0..7
    const int qid  = lane & 3;       // 0..3
    const int wm   = (wid & 1) * 64; // warp M offset
    const int wn   = (wid >> 1) * 32;// warp N offset
    const int rowA = blockIdx.y * 128;
    const int colB = blockIdx.x * 128;

    float acc[4][4][4];
#pragma unroll
    for (int i = 0; i < 4; i++)
#pragma unroll
        for (int j = 0; j < 4; j++)
#pragma unroll
            for (int q = 0; q < 4; q++) acc[i][j][q] = 0.0f;

    // tile loader: 4 tiles (Ahi, Alo, Bhi, Blo), each 128 rows x 32 bf16
    auto load_tiles = [&](int buf, int k0) {
        __nv_bfloat16* base = smem + buf * 4 * GTILE;
#pragma unroll
        for (int c = tid; c < 512; c += 256) {
            int row = c >> 2, off = (c & 3) * 8;
            size_t ga = (size_t)(rowA + row) * K + k0 + off;
            size_t gb = (size_t)(colB + row) * K + k0 + off;
            int so = row * PADK + off;
            cpa16(base + 0 * GTILE + so, Ahi + ga);
            cpa16(base + 1 * GTILE + so, Alo + ga);
            cpa16(base + 2 * GTILE + so, Bhi + gb);
            cpa16(base + 3 * GTILE + so, Blo + gb);
        }
    };

    const int NT = K / 32;
    load_tiles(0, 0);
    cp_commit();

    for (int kt = 0; kt < NT; kt++) {
        if (kt + 1 < NT) {
            load_tiles((kt + 1) & 1, (kt + 1) * 32);
            cp_commit();
            cp_wait<1>();
        } else {
            cp_wait<0>();
        }
        __syncthreads();

        const __nv_bfloat16* base = smem + (kt & 1) * 4 * GTILE;
        const __nv_bfloat16* sAh = base + 0 * GTILE;
        const __nv_bfloat16* sAl = base + 1 * GTILE;
        const __nv_bfloat16* sBh = base + 2 * GTILE;
        const __nv_bfloat16* sBl = base + 3 * GTILE;

#pragma unroll
        for (int kh = 0; kh < 2; kh++) {
            const int kb = (kh * 16 + qid * 2) >> 1;   // b32 index within row
            uint32_t ah[4][4], al[4][4], bh[4][2], bl[4][2];
#pragma unroll
            for (int mt = 0; mt < 4; mt++) {
                int r0 = wm + mt * 16 + grp;
                const uint32_t* p0h = (const uint32_t*)(sAh + r0 * PADK);
                const uint32_t* p1h = (const uint32_t*)(sAh + (r0 + 8) * PADK);
                const uint32_t* p0l = (const uint32_t*)(sAl + r0 * PADK);
                const uint32_t* p1l = (const uint32_t*)(sAl + (r0 + 8) * PADK);
                ah[mt][0] = p0h[kb];     ah[mt][1] = p1h[kb];
                ah[mt][2] = p0h[kb + 4]; ah[mt][3] = p1h[kb + 4];
                al[mt][0] = p0l[kb];     al[mt][1] = p1l[kb];
                al[mt][2] = p0l[kb + 4]; al[mt][3] = p1l[kb + 4];
            }
#pragma unroll
            for (int nt = 0; nt < 4; nt++) {
                int c0 = wn + nt * 8 + grp;
                const uint32_t* pbh = (const uint32_t*)(sBh + c0 * PADK);
                const uint32_t* pbl = (const uint32_t*)(sBl + c0 * PADK);
                bh[nt][0] = pbh[kb]; bh[nt][1] = pbh[kb + 4];
                bl[nt][0] = pbl[kb]; bl[nt][1] = pbl[kb + 4];
            }
#pragma unroll
            for (int mt = 0; mt < 4; mt++)
#pragma unroll
                for (int nt = 0; nt < 4; nt++) {
                    mma16816(acc[mt][nt], ah[mt], bh[nt]);
                    mma16816(acc[mt][nt], ah[mt], bl[nt]);
                    mma16816(acc[mt][nt], al[mt], bh[nt]);
                }
        }
        __syncthreads();
    }

    // epilogue: + bias, fp32 store
#pragma unroll
    for (int mt = 0; mt < 4; mt++) {
        int r = rowA + wm + mt * 16 + grp;
#pragma unroll
        for (int nt = 0; nt < 4; nt++) {
            int cc = colB + wn + nt * 8 + qid * 2;
            float b0 = bias[cc], b1 = bias[cc + 1];
            float2 v0 = make_float2(acc[mt][nt][0] + b0, acc[mt][nt][1] + b1);
            float2 v1 = make_float2(acc[mt][nt][2] + b0, acc[mt][nt][3] + b1);
            *(float2*)(C + (size_t)r * N + cc)       = v0;
            *(float2*)(C + (size_t)(r + 8) * N + cc) = v1;
        }
    }
}

// ---------------------------------------------------------------------------
// RoPE (unchanged)
// ---------------------------------------------------------------------------
__global__ void rope_kernel(float* __restrict__ t,
                            const float* __restrict__ fc,
                            const float* __restrict__ fs,
                            int nheads)
{
    int idx = blockIdx.x * blockDim.x + threadIdx.x;
    int total = B_ * S_ * nheads * (HD_ / 2);
    if (idx >= total) return;
    int p = idx & 63;
    int h = (idx >> 6) % nheads;
    int s = (idx / (64 * nheads)) % S_;
    int b = idx / (64 * nheads * S_);
    float c  = fc[s * 64 + p];
    float sn = fs[s * 64 + p];
    float* base = t + ((size_t)(b * S_ + s) * nheads + h) * HD_ + 2 * p;
    float re = base[0], im = base[1];
    base[0] = re * c - im * sn;
    base[1] = re * sn + im * c;
}

// ---------------------------------------------------------------------------
// Attention (unchanged from R1): one CTA per (b,h), fp32 SIMT
// ---------------------------------------------------------------------------
#define PAD 132
#define ATT_SMEM (3 * 128 * PAD * (int)sizeof(float))

__global__ __launch_bounds__(256) void attn_kernel(
    const float* __restrict__ q, const float* __restrict__ k,
    const float* __restrict__ v, float* __restrict__ o)
{
    extern __shared__ __align__(16) float sm[];
    float (*sQ)[PAD]  = (float(*)[PAD])sm;
    float (*sKt)[PAD] = (float(*)[PAD])(sm + 128 * PAD);
    float (*sS)[PAD]  = (float(*)[PAD])(sm + 2 * 128 * PAD);

    const int h = blockIdx.x;
    const int b = blockIdx.y;
    const int kvh = h >> 2;
    const int tx = threadIdx.x, ty = threadIdx.y;
    const int tid = ty * 16 + tx;

    for (int idx = tid; idx < 128 * 128; idx += 256) {
        int r = idx >> 7, c = idx & 127;
        sQ[r][c]  = q[((size_t)(b * S_ + r) * H_  + h)   * HD_ + c];
        sKt[c][r] = k[((size_t)(b * S_ + r) * KV_ + kvh) * HD_ + c];
    }
    __syncthreads();

    float acc[8][8];
#pragma unroll
    for (int i = 0; i < 8; i++)
#pragma unroll
        for (int j = 0; j < 8; j++) acc[i][j] = 0.0f;

#pragma unroll 4
    for (int d = 0; d < 128; d++) {
        float rA[8], rB[8];
#pragma unroll
        for (int i = 0; i < 8; i++) rA[i] = sQ[ty * 8 + i][d];
        float4 b0 = *(const float4*)&sKt[d][tx * 8];
        float4 b1 = *(const float4*)&sKt[d][tx * 8 + 4];
        rB[0] = b0.x; rB[1] = b0.y; rB[2] = b0.z; rB[3] = b0.w;
        rB[4] = b1.x; rB[5] = b1.y; rB[6] = b1.z; rB[7] = b1.w;
#pragma unroll
        for (int i = 0; i < 8; i++)
#pragma unroll
            for (int j = 0; j < 8; j++)
                acc[i][j] = fmaf(rA[i], rB[j], acc[i][j]);
    }

    const float scale = 0.08838834764831845f;
#pragma unroll
    for (int i = 0; i < 8; i++) {
        int r = ty * 8 + i;
#pragma unroll
        for (int j = 0; j < 8; j++) {
            int c = tx * 8 + j;
            sS[r][c] = (c <= r) ? acc[i][j] * scale : -1e30f;
        }
    }
    __syncthreads();

    {
        int wid = tid >> 5, lane = tid & 31;
        for (int r = wid; r < 128; r += 8) {
            float v0 = sS[r][lane],      v1 = sS[r][lane + 32];
            float v2 = sS[r][lane + 64], v3 = sS[r][lane + 96];
            float m = fmaxf(fmaxf(v0, v1), fmaxf(v2, v3));
#pragma unroll
            for (int o2 = 16; o2; o2 >>= 1) m = fmaxf(m, __shfl_xor_sync(0xffffffffu, m, o2));
            v0 = __expf(v0 - m); v1 = __expf(v1 - m);
            v2 = __expf(v2 - m); v3 = __expf(v3 - m);
            float s = v0 + v1 + v2 + v3;
#pragma unroll
            for (int o2 = 16; o2; o2 >>= 1) s += __shfl_xor_sync(0xffffffffu, s, o2);
            float inv = 1.0f / s;
            sS[r][lane]      = v0 * inv; sS[r][lane + 32] = v1 * inv;
            sS[r][lane + 64] = v2 * inv; sS[r][lane + 96] = v3 * inv;
        }
        float (*sV)[PAD] = sKt;
        for (int idx = tid; idx < 128 * 128; idx += 256) {
            int r = idx >> 7, c = idx & 127;
            sV[r][c] = v[((size_t)(b * S_ + r) * KV_ + kvh) * HD_ + c];
        }
    }
    __syncthreads();

    float (*sV)[PAD] = sKt;
#pragma unroll
    for (int i = 0; i < 8; i++)
#pragma unroll
        for (int j = 0; j < 8; j++) acc[i][j] = 0.0f;

#pragma unroll 4
    for (int j = 0; j < 128; j++) {
        float rA[8], rB[8];
#pragma unroll
        for (int i = 0; i < 8; i++) rA[i] = sS[ty * 8 + i][j];
        float4 b0 = *(const float4*)&sV[j][tx * 8];
        float4 b1 = *(const float4*)&sV[j][tx * 8 + 4];
        rB[0] = b0.x; rB[1] = b0.y; rB[2] = b0.z; rB[3] = b0.w;
        rB[4] = b1.x; rB[5] = b1.y; rB[6] = b1.z; rB[7] = b1.w;
#pragma unroll
        for (int i = 0; i < 8; i++)
#pragma unroll
            for (int jj = 0; jj < 8; jj++)
                acc[i][jj] = fmaf(rA[i], rB[jj], acc[i][jj]);
    }

#pragma unroll
    for (int i = 0; i < 8; i++) {
        int r = ty * 8 + i;
        float* dst = o + ((size_t)(b * S_ + r) * H_ + h) * HD_ + tx * 8;
        *(float4*)(dst)     = make_float4(acc[i][0], acc[i][1], acc[i][2], acc[i][3]);
        *(float4*)(dst + 4) = make_float4(acc[i][4], acc[i][5], acc[i][6], acc[i][7]);
    }
}

// ---------------------------------------------------------------------------
// Launch
// Inputs: 0:x 1:start_pos 2:freqs_cos 3:freqs_sin 4:mask 5:cache_k 6:cache_v
//         7:wq 8:bq 9:wk 10:bk 11:wv 12:bv 13:wo 14:bo
// ---------------------------------------------------------------------------
extern "C" void kernel_launch(void* const* d_in, const int* in_sizes, int n_in,
                              void* d_out, int out_size)
{
    const float* x    = (const float*)d_in[0];
    const float* fcos = (const float*)d_in[2];
    const float* fsin = (const float*)d_in[3];
    const float* wq   = (const float*)d_in[7];
    const float* bq   = (const float*)d_in[8];
    const float* wk   = (const float*)d_in[9];
    const float* bk   = (const float*)d_in[10];
    const float* wv   = (const float*)d_in[11];
    const float* bv   = (const float*)d_in[12];
    const float* wo   = (const float*)d_in[13];
    const float* bo   = (const float*)d_in[14];
    float* out = (float*)d_out;

    float *pq, *pk, *pv, *patt;
    __nv_bfloat16 *xh, *xl, *ah, *al;
    __nv_bfloat16 *wqh, *wql, *wkh, *wkl, *wvh, *wvl, *woh, *wol;
    cudaGetSymbolAddress((void**)&pq,   g_q);
    cudaGetSymbolAddress((void**)&pk,   g_k);
    cudaGetSymbolAddress((void**)&pv,   g_v);
    cudaGetSymbolAddress((void**)&patt, g_att);
    cudaGetSymbolAddress((void**)&xh,  g_xh);  cudaGetSymbolAddress((void**)&xl,  g_xl);
    cudaGetSymbolAddress((void**)&ah,  g_ah);  cudaGetSymbolAddress((void**)&al,  g_al);
    cudaGetSymbolAddress((void**)&wqh, g_wqh); cudaGetSymbolAddress((void**)&wql, g_wql);
    cudaGetSymbolAddress((void**)&wkh, g_wkh); cudaGetSymbolAddress((void**)&wkl, g_wkl);
    cudaGetSymbolAddress((void**)&wvh, g_wvh); cudaGetSymbolAddress((void**)&wvl, g_wvl);
    cudaGetSymbolAddress((void**)&woh, g_woh); cudaGetSymbolAddress((void**)&wol, g_wol);

    cudaFuncSetAttribute(attn_kernel, cudaFuncAttributeMaxDynamicSharedMemorySize, ATT_SMEM);
    cudaFuncSetAttribute(gemm_mma_split, cudaFuncAttributeMaxDynamicSharedMemorySize, GSMEM);

    // --- split activations + weights ---
    split_rows<<<(M_ * D_ / 2 + 255) / 256, 256>>>(x, xh, xl, M_ * D_);
    split_transpose<<<dim3(D_ / 32, D_ / 32), dim3(32, 8)>>>(wq, wqh, wql, D_, D_);
    split_transpose<<<dim3((KV_ * HD_) / 32, D_ / 32), dim3(32, 8)>>>(wk, wkh, wkl, D_, KV_ * HD_);
    split_transpose<<<dim3((KV_ * HD_) / 32, D_ / 32), dim3(32, 8)>>>(wv, wvh, wvl, D_, KV_ * HD_);
    split_transpose<<<dim3(D_ / 32, D_ / 32), dim3(32, 8)>>>(wo, woh, wol, D_, D_);

    // --- QKV projections (tensor core) ---
    gemm_mma_split<<<dim3((H_ * HD_) / 128, M_ / 128), 256, GSMEM>>>(
        xh, xl, wqh, wql, bq, pq, M_, H_ * HD_, D_);
    gemm_mma_split<<<dim3((KV_ * HD_) / 128, M_ / 128), 256, GSMEM>>>(
        xh, xl, wkh, wkl, bk, pk, M_, KV_ * HD_, D_);
    gemm_mma_split<<<dim3((KV_ * HD_) / 128, M_ / 128), 256, GSMEM>>>(
        xh, xl, wvh, wvl, bv, pv, M_, KV_ * HD_, D_);

    // --- RoPE ---
    {
        int tq = B_ * S_ * H_ * (HD_ / 2);
        int tk = B_ * S_ * KV_ * (HD_ / 2);
        rope_kernel<<<(tq + 255) / 256, 256>>>(pq, fcos, fsin, H_);
        rope_kernel<<<(tk + 255) / 256, 256>>>(pk, fcos, fsin, KV_);
    }

    // --- attention ---
    attn_kernel<<<dim3(H_, B_), dim3(16, 16), ATT_SMEM>>>(pq, pk, pv, patt);

    // --- output projection ---
    split_rows<<<(M_ * D_ / 2 + 255) / 256, 256>>>(patt, ah, al, M_ * D_);
    gemm_mma_split<<<dim3(D_ / 128, M_ / 128), 256, GSMEM>>>(
        ah, al, woh, wol, bo, out, M_, D_, D_);
}